// round 3
// baseline (speedup 1.0000x reference)
#include <cuda_runtime.h>
#include <cuda_bf16.h>
#include <math.h>

// ---------------------------------------------------------------------------
// Scratch buffers (device globals; allocation-free)
// ---------------------------------------------------------------------------
__device__ float g_bufA[64 * 128 * 128];   // 4 MB  — pre-norm activations
__device__ float g_bufB[64 * 64 * 64];     // 1 MB  — ping
__device__ float g_bufC[64 * 64 * 64];     // 1 MB  — pong
__device__ float g_accS[64];               // per-image sum   (zero-init, re-zeroed each use)
__device__ float g_accQ[64];               // per-image sumsq

// ---------------------------------------------------------------------------
// Locally-connected layer:  act[b,i,j] = relu( sum_{kh,kw} in[b,i-P+kh,j-P+kw] * w[i,j,kh,kw] + bias[i,j] )
// Also accumulates per-image sum / sumsq for the following LayerNorm.
// Block: RPB output rows x W cols (blockDim = RPB*W = 128), loops over BCH batch images.
// Weights for this block's pixels are held in registers; input tile staged in smem.
// ---------------------------------------------------------------------------
template <int H, int K, int PAD, int RPB, int BCH>
__global__ __launch_bounds__(128) void lc_kernel(const float* __restrict__ in,
                                                 const float* __restrict__ w,
                                                 const float* __restrict__ bias,
                                                 float* __restrict__ act,
                                                 float* __restrict__ accS,
                                                 float* __restrict__ accQ) {
    constexpr int W  = H;
    constexpr int KK = K * K;
    constexpr int IW = W + 2 * PAD;
    constexpr int IR = RPB + 2 * PAD;
    constexpr int NT = RPB * W;            // threads per block (=128)
    constexpr int NW = NT / 32;            // warps

    __shared__ float sin[IR * IW];
    __shared__ float sred[2 * NW];

    const int r0  = blockIdx.x * RPB;
    const int b0  = blockIdx.y * BCH;
    const int tid = threadIdx.x;
    const int li  = tid / W;
    const int lj  = tid % W;
    const int i   = r0 + li;
    const int j   = lj;

    // Per-pixel weights -> registers (reused across BCH images)
    float wr[KK];
    const float* wp = w + (size_t)(i * W + j) * KK;
#pragma unroll
    for (int t = 0; t < KK; t++) wr[t] = wp[t];
    const float bb = bias[i * W + j];

    for (int bi = 0; bi < BCH; bi++) {
        const int b = b0 + bi;
        const float* inb = in + (size_t)b * H * W;
        __syncthreads();
        // stage padded input tile
        for (int idx = tid; idx < IR * IW; idx += NT) {
            int r  = idx / IW, c = idx % IW;
            int gi = r0 - PAD + r;
            int gj = c - PAD;
            float v = 0.f;
            if (gi >= 0 && gi < H && gj >= 0 && gj < W) v = inb[gi * W + gj];
            sin[idx] = v;
        }
        __syncthreads();

        float sum = bb;
#pragma unroll
        for (int kh = 0; kh < K; kh++)
#pragma unroll
            for (int kw = 0; kw < K; kw++)
                sum = fmaf(wr[kh * K + kw], sin[(li + kh) * IW + (lj + kw)], sum);

        float v = fmaxf(sum, 0.f);
        act[(size_t)b * H * W + i * W + j] = v;

        // block-reduce sum & sumsq for this image
        float s = v, q = v * v;
#pragma unroll
        for (int o = 16; o > 0; o >>= 1) {
            s += __shfl_down_sync(0xffffffffu, s, o);
            q += __shfl_down_sync(0xffffffffu, q, o);
        }
        const int wid = tid >> 5, lane = tid & 31;
        if (lane == 0) { sred[wid] = s; sred[NW + wid] = q; }
        __syncthreads();
        if (tid == 0) {
            float ts = 0.f, tq = 0.f;
#pragma unroll
            for (int k = 0; k < NW; k++) { ts += sred[k]; tq += sred[NW + k]; }
            atomicAdd(&accS[b], ts);
            atomicAdd(&accQ[b], tq);
        }
    }
}

// ---------------------------------------------------------------------------
// LayerNorm over spatial dims (per image) + optional 2x2 maxpool.
// One block per image. Re-zeroes the accumulators (graph-replay determinism).
// ---------------------------------------------------------------------------
template <int H, bool POOL>
__global__ __launch_bounds__(256) void norm_kernel(const float* __restrict__ act,
                                                   const float* __restrict__ g,
                                                   const float* __restrict__ be,
                                                   float* __restrict__ out,
                                                   float* __restrict__ accS,
                                                   float* __restrict__ accQ) {
    constexpr int W = H;
    constexpr int N = H * W;
    const int b = blockIdx.x;

    __shared__ float s_mean, s_rstd;
    if (threadIdx.x == 0) {
        float s = accS[b], q = accQ[b];
        float mean = s / (float)N;
        float var  = q / (float)N - mean * mean;
        s_mean = mean;
        s_rstd = rsqrtf(var + 1e-5f);
        accS[b] = 0.f;
        accQ[b] = 0.f;
    }
    __syncthreads();
    const float mean = s_mean, rstd = s_rstd;
    const float* ab = act + (size_t)b * N;

    if (!POOL) {
        for (int p = threadIdx.x; p < N; p += blockDim.x) {
            out[(size_t)b * N + p] = (ab[p] - mean) * rstd * g[p] + be[p];
        }
    } else {
        constexpr int HO = H / 2;
        for (int p = threadIdx.x; p < HO * HO; p += blockDim.x) {
            int oi = p / HO, oj = p % HO;
            int i0 = oi * 2, j0 = oj * 2;
            float m = -INFINITY;
#pragma unroll
            for (int di = 0; di < 2; di++)
#pragma unroll
                for (int dj = 0; dj < 2; dj++) {
                    int idx = (i0 + di) * W + (j0 + dj);
                    float v = (ab[idx] - mean) * rstd * g[idx] + be[idx];
                    m = fmaxf(m, v);
                }
            out[(size_t)b * HO * HO + p] = m;
        }
    }
}

// ---------------------------------------------------------------------------
// FC [64,256] @ fcw^T [256,1024] + fcb, then softmax over 1024.
// Grid: 16 blocks, each handles 4 images (weight rows reused 4x).
// ---------------------------------------------------------------------------
__global__ __launch_bounds__(256) void fc_softmax_kernel(const float* __restrict__ h,
                                                         const float* __restrict__ fcw,
                                                         const float* __restrict__ fcb,
                                                         float* __restrict__ out) {
    __shared__ float sh[4][256];
    __shared__ float sred[8][4];
    const int tid = threadIdx.x;
    const int b0  = blockIdx.x * 4;

#pragma unroll
    for (int bi = 0; bi < 4; bi++) sh[bi][tid] = h[(size_t)(b0 + bi) * 256 + tid];
    __syncthreads();

    float l[4][4];  // [r][bi]
#pragma unroll
    for (int r = 0; r < 4; r++) {
        const int o = tid + r * 256;
        const float* wrow = fcw + (size_t)o * 256;
        const float bias = fcb[o];
        float a0 = bias, a1 = bias, a2 = bias, a3 = bias;
#pragma unroll 4
        for (int k = 0; k < 256; k++) {
            float wv = wrow[k];
            a0 = fmaf(wv, sh[0][k], a0);
            a1 = fmaf(wv, sh[1][k], a1);
            a2 = fmaf(wv, sh[2][k], a2);
            a3 = fmaf(wv, sh[3][k], a3);
        }
        l[r][0] = a0; l[r][1] = a1; l[r][2] = a2; l[r][3] = a3;
    }

    const int wid = tid >> 5, lane = tid & 31;

    // ---- block max per image ----
    float mx[4];
#pragma unroll
    for (int bi = 0; bi < 4; bi++) {
        float m = l[0][bi];
#pragma unroll
        for (int r = 1; r < 4; r++) m = fmaxf(m, l[r][bi]);
        mx[bi] = m;
    }
#pragma unroll
    for (int o = 16; o > 0; o >>= 1)
#pragma unroll
        for (int bi = 0; bi < 4; bi++)
            mx[bi] = fmaxf(mx[bi], __shfl_xor_sync(0xffffffffu, mx[bi], o));
    if (lane == 0)
#pragma unroll
        for (int bi = 0; bi < 4; bi++) sred[wid][bi] = mx[bi];
    __syncthreads();
    float M[4];
#pragma unroll
    for (int bi = 0; bi < 4; bi++) {
        float m = sred[0][bi];
#pragma unroll
        for (int wgt = 1; wgt < 8; wgt++) m = fmaxf(m, sred[wgt][bi]);
        M[bi] = m;
    }
    __syncthreads();  // before sred reuse

    // ---- block sum of exp per image ----
    float sm[4] = {0.f, 0.f, 0.f, 0.f};
#pragma unroll
    for (int r = 0; r < 4; r++)
#pragma unroll
        for (int bi = 0; bi < 4; bi++) sm[bi] += expf(l[r][bi] - M[bi]);
#pragma unroll
    for (int o = 16; o > 0; o >>= 1)
#pragma unroll
        for (int bi = 0; bi < 4; bi++)
            sm[bi] += __shfl_xor_sync(0xffffffffu, sm[bi], o);
    if (lane == 0)
#pragma unroll
        for (int bi = 0; bi < 4; bi++) sred[wid][bi] = sm[bi];
    __syncthreads();
    float S[4];
#pragma unroll
    for (int bi = 0; bi < 4; bi++) {
        float s = 0.f;
#pragma unroll
        for (int wgt = 0; wgt < 8; wgt++) s += sred[wgt][bi];
        S[bi] = 1.0f / s;
    }

    // ---- write normalized probabilities ----
#pragma unroll
    for (int r = 0; r < 4; r++) {
        const int o = tid + r * 256;
#pragma unroll
        for (int bi = 0; bi < 4; bi++)
            out[(size_t)(b0 + bi) * 1024 + o] = expf(l[r][bi] - M[bi]) * S[bi];
    }
}

// ---------------------------------------------------------------------------
// Launch
// ---------------------------------------------------------------------------
extern "C" void kernel_launch(void* const* d_in, const int* in_sizes, int n_in,
                              void* d_out, int out_size) {
    (void)in_sizes; (void)n_in; (void)out_size;

    const float* x   = (const float*)d_in[0];
    const float* w1  = (const float*)d_in[1];
    const float* b1  = (const float*)d_in[2];
    const float* g1  = (const float*)d_in[3];
    const float* be1 = (const float*)d_in[4];
    const float* w2  = (const float*)d_in[5];
    const float* b2  = (const float*)d_in[6];
    const float* g2  = (const float*)d_in[7];
    const float* be2 = (const float*)d_in[8];
    const float* w3  = (const float*)d_in[9];
    const float* b3  = (const float*)d_in[10];
    const float* g3  = (const float*)d_in[11];
    const float* be3 = (const float*)d_in[12];
    const float* w4  = (const float*)d_in[13];
    const float* b4  = (const float*)d_in[14];
    const float* g4  = (const float*)d_in[15];
    const float* be4 = (const float*)d_in[16];
    const float* w5  = (const float*)d_in[17];
    const float* b5  = (const float*)d_in[18];
    const float* g5  = (const float*)d_in[19];
    const float* be5 = (const float*)d_in[20];
    const float* w6  = (const float*)d_in[21];
    const float* b6  = (const float*)d_in[22];
    const float* g6  = (const float*)d_in[23];
    const float* be6 = (const float*)d_in[24];
    const float* fcw = (const float*)d_in[25];
    const float* fcb = (const float*)d_in[26];
    float* out = (float*)d_out;

    float *A, *B, *C, *aS, *aQ;
    cudaGetSymbolAddress((void**)&A,  g_bufA);
    cudaGetSymbolAddress((void**)&B,  g_bufB);
    cudaGetSymbolAddress((void**)&C,  g_bufC);
    cudaGetSymbolAddress((void**)&aS, g_accS);
    cudaGetSymbolAddress((void**)&aQ, g_accQ);

    // L1: 128x128, k=7, pad=3  -> pool -> 64x64
    lc_kernel<128, 7, 3, 1, 16><<<dim3(128, 4), 128>>>(x, w1, b1, A, aS, aQ);
    norm_kernel<128, true><<<64, 256>>>(A, g1, be1, B, aS, aQ);

    // L2: 64x64, k=5, pad=2
    lc_kernel<64, 5, 2, 2, 16><<<dim3(32, 4), 128>>>(B, w2, b2, A, aS, aQ);
    norm_kernel<64, false><<<64, 256>>>(A, g2, be2, C, aS, aQ);

    // L3: 64x64, k=5, pad=2 -> pool -> 32x32
    lc_kernel<64, 5, 2, 2, 16><<<dim3(32, 4), 128>>>(C, w3, b3, A, aS, aQ);
    norm_kernel<64, true><<<64, 256>>>(A, g3, be3, B, aS, aQ);

    // L4: 32x32, k=3, pad=1
    lc_kernel<32, 3, 1, 4, 16><<<dim3(8, 4), 128>>>(B, w4, b4, A, aS, aQ);
    norm_kernel<32, false><<<64, 256>>>(A, g4, be4, C, aS, aQ);

    // L5: 32x32, k=3, pad=1 -> pool -> 16x16
    lc_kernel<32, 3, 1, 4, 16><<<dim3(8, 4), 128>>>(C, w5, b5, A, aS, aQ);
    norm_kernel<32, true><<<64, 256>>>(A, g5, be5, B, aS, aQ);

    // L6: 16x16, k=3, pad=1
    lc_kernel<16, 3, 1, 8, 16><<<dim3(2, 4), 128>>>(B, w6, b6, A, aS, aQ);
    norm_kernel<16, false><<<64, 256>>>(A, g6, be6, C, aS, aQ);

    // FC + softmax
    fc_softmax_kernel<<<16, 256>>>(C, fcw, fcb, out);
}

// round 4
// speedup vs baseline: 2.9646x; 2.9646x over previous
#include <cuda_runtime.h>
#include <cuda_bf16.h>
#include <math.h>

// ---------------------------------------------------------------------------
// Scratch: pre-norm L1 activations (allocation-free device global)
// ---------------------------------------------------------------------------
__device__ float g_bufA[64 * 128 * 128];   // 4 MB

// ===========================================================================
// Kernel A: L1 locally-connected + ReLU.  Weights (49/pixel) in registers,
// reused across BCH images.  Writes pre-norm activations to gmem.
// Block: RPB rows x 128 cols = 512 threads. Grid: (128/RPB, 64/BCH).
// ===========================================================================
template <int RPB, int BCH>
__global__ __launch_bounds__(512) void lc1_kernel(const float* __restrict__ in,
                                                  const float* __restrict__ w,
                                                  const float* __restrict__ bias,
                                                  float* __restrict__ act) {
    constexpr int H = 128, W = 128, K = 7, PAD = 3, KK = 49;
    constexpr int IW = W + 2 * PAD;        // 134
    constexpr int IR = RPB + 2 * PAD;      // RPB+6
    constexpr int NT = RPB * W;            // 512

    __shared__ float sin[IR * IW];

    const int r0  = blockIdx.x * RPB;
    const int b0  = blockIdx.y * BCH;
    const int tid = threadIdx.x;
    const int li  = tid / W;
    const int lj  = tid % W;
    const int i   = r0 + li;
    const int j   = lj;

    float wr[KK];
    const float* wp = w + (size_t)(i * W + j) * KK;
#pragma unroll
    for (int t = 0; t < KK; t++) wr[t] = wp[t];
    const float bb = bias[i * W + j];

    for (int bi = 0; bi < BCH; bi++) {
        const int b = b0 + bi;
        const float* inb = in + (size_t)b * H * W;
        __syncthreads();
        for (int idx = tid; idx < IR * IW; idx += NT) {
            int r = idx / IW, c = idx % IW;
            int gi = r0 - PAD + r;
            int gj = c - PAD;
            float v = 0.f;
            if (gi >= 0 && gi < H && gj >= 0 && gj < W) v = inb[gi * W + gj];
            sin[idx] = v;
        }
        __syncthreads();

        float sum = bb;
#pragma unroll
        for (int kh = 0; kh < K; kh++)
#pragma unroll
            for (int kw = 0; kw < K; kw++)
                sum = fmaf(wr[kh * K + kw], sin[(li + kh) * IW + (lj + kw)], sum);

        act[(size_t)b * H * W + i * W + j] = fmaxf(sum, 0.f);
    }
}

// ===========================================================================
// Kernel B: everything else, fused.  One block per image, 1024 threads.
// All intermediates in shared memory; LayerNorm stats via block reduction.
// ===========================================================================
#define NTB 1024
#define PW  68    // padded buffer row width (max 64 + 2*2)

// ---- block-wide sum of (s,q); red must have >= 64 floats -----------------
__device__ __forceinline__ void block_sum2(float& s, float& q, float* red) {
    __syncthreads();   // protect red reuse (WAR vs previous reduce's readers)
#pragma unroll
    for (int o = 16; o > 0; o >>= 1) {
        s += __shfl_down_sync(0xffffffffu, s, o);
        q += __shfl_down_sync(0xffffffffu, q, o);
    }
    const int wid = threadIdx.x >> 5, lane = threadIdx.x & 31;
    if (lane == 0) { red[wid] = s; red[32 + wid] = q; }
    __syncthreads();
    if (wid == 0) {
        s = red[lane]; q = red[32 + lane];
#pragma unroll
        for (int o = 16; o > 0; o >>= 1) {
            s += __shfl_down_sync(0xffffffffu, s, o);
            q += __shfl_down_sync(0xffffffffu, q, o);
        }
        if (lane == 0) { red[0] = s; red[32] = q; }
    }
    __syncthreads();
    s = red[0]; q = red[32];
}

__device__ __forceinline__ float block_max(float v, float* red) {
    __syncthreads();
#pragma unroll
    for (int o = 16; o > 0; o >>= 1)
        v = fmaxf(v, __shfl_xor_sync(0xffffffffu, v, o));
    const int wid = threadIdx.x >> 5, lane = threadIdx.x & 31;
    if (lane == 0) red[wid] = v;
    __syncthreads();
    if (wid == 0) {
        v = red[lane];
#pragma unroll
        for (int o = 16; o > 0; o >>= 1)
            v = fmaxf(v, __shfl_xor_sync(0xffffffffu, v, o));
        if (lane == 0) red[0] = v;
    }
    __syncthreads();
    return red[0];
}

__device__ __forceinline__ float block_sum1(float v, float* red) {
    __syncthreads();
#pragma unroll
    for (int o = 16; o > 0; o >>= 1)
        v += __shfl_down_sync(0xffffffffu, v, o);
    const int wid = threadIdx.x >> 5, lane = threadIdx.x & 31;
    if (lane == 0) red[wid] = v;
    __syncthreads();
    if (wid == 0) {
        v = red[lane];
#pragma unroll
        for (int o = 16; o > 0; o >>= 1)
            v += __shfl_down_sync(0xffffffffu, v, o);
        if (lane == 0) red[0] = v;
    }
    __syncthreads();
    return red[0];
}

// ---- LC layer from padded smem; relu; stats -------------------------------
// s_in: padded buffer, interior origin (PAD,PAD) so index is (i+kh)*PW+(j+kw).
template <int H, int K>
__device__ __forceinline__ void lc_sm(const float* __restrict__ w,
                                      const float* __restrict__ bias,
                                      const float* s_in, float* s_act,
                                      float& mean, float& rstd, float* red) {
    float s = 0.f, q = 0.f;
    for (int p = threadIdx.x; p < H * H; p += NTB) {
        const int i = p / H, j = p % H;
        const float* wp = w + (size_t)p * K * K;
        float acc = bias[p];
#pragma unroll
        for (int kh = 0; kh < K; kh++)
#pragma unroll
            for (int kw = 0; kw < K; kw++)
                acc = fmaf(wp[kh * K + kw], s_in[(i + kh) * PW + (j + kw)], acc);
        float v = fmaxf(acc, 0.f);
        s_act[p] = v;
        s += v; q += v * v;
    }
    block_sum2(s, q, red);
    const float m = s * (1.0f / (H * H));
    mean = m;
    rstd = rsqrtf(q * (1.0f / (H * H)) - m * m + 1e-5f);
}

// ---- normalize (+optional 2x2 pool) into padded buffer (origin OPAD) ------
template <int H, bool POOL, int OPAD, bool FLAT>
__device__ __forceinline__ void norm_store(const float* s_act,
                                           const float* __restrict__ g,
                                           const float* __restrict__ be,
                                           float mean, float rstd, float* s_pad) {
    // zero whole padded buffer (clears stale halo)
    for (int p = threadIdx.x; p < PW * PW; p += NTB) s_pad[p] = 0.f;
    __syncthreads();
    if (!POOL) {
        for (int p = threadIdx.x; p < H * H; p += NTB) {
            const int i = p / H, j = p % H;
            float v = (s_act[p] - mean) * rstd * g[p] + be[p];
            if (FLAT) s_pad[p] = v;
            else      s_pad[(i + OPAD) * PW + (j + OPAD)] = v;
        }
    } else {
        constexpr int HO = H / 2;
        for (int p = threadIdx.x; p < HO * HO; p += NTB) {
            const int oi = p / HO, oj = p % HO;
            float m = -INFINITY;
#pragma unroll
            for (int di = 0; di < 2; di++)
#pragma unroll
                for (int dj = 0; dj < 2; dj++) {
                    const int idx = (2 * oi + di) * H + (2 * oj + dj);
                    float v = (s_act[idx] - mean) * rstd * g[idx] + be[idx];
                    m = fmaxf(m, v);
                }
            s_pad[(oi + OPAD) * PW + (oj + OPAD)] = m;
        }
    }
    __syncthreads();
}

__global__ __launch_bounds__(NTB) void fused_kernel(
    const float* __restrict__ bufA,
    const float* __restrict__ g1, const float* __restrict__ be1,
    const float* __restrict__ w2, const float* __restrict__ b2,
    const float* __restrict__ g2, const float* __restrict__ be2,
    const float* __restrict__ w3, const float* __restrict__ b3,
    const float* __restrict__ g3, const float* __restrict__ be3,
    const float* __restrict__ w4, const float* __restrict__ b4,
    const float* __restrict__ g4, const float* __restrict__ be4,
    const float* __restrict__ w5, const float* __restrict__ b5,
    const float* __restrict__ g5, const float* __restrict__ be5,
    const float* __restrict__ w6, const float* __restrict__ b6,
    const float* __restrict__ g6, const float* __restrict__ be6,
    const float* __restrict__ fcw, const float* __restrict__ fcb,
    float* __restrict__ out) {

    __shared__ float s_pad[PW * PW];   // 4624 floats
    __shared__ float s_act[64 * 64];   // 4096 floats
    __shared__ float s_red[64];

    const int b   = blockIdx.x;
    const int tid = threadIdx.x;
    const float* ab = bufA + (size_t)b * 128 * 128;

    // ---------------- L1 stats from gmem (vectorized) ----------------------
    {
        float s = 0.f, q = 0.f;
        const float4* a4 = (const float4*)ab;
        for (int p = tid; p < 128 * 128 / 4; p += NTB) {
            float4 v = a4[p];
            s += v.x + v.y + v.z + v.w;
            q += v.x * v.x + v.y * v.y + v.z * v.z + v.w * v.w;
        }
        block_sum2(s, q, s_red);
        const float mean = s * (1.0f / 16384.0f);
        const float rstd = rsqrtf(q * (1.0f / 16384.0f) - mean * mean + 1e-5f);

        // norm1 + pool 128->64, write into padded buffer (OPAD=2 for k=5)
        for (int p = tid; p < PW * PW; p += NTB) s_pad[p] = 0.f;
        __syncthreads();
        for (int p = tid; p < 64 * 64; p += NTB) {
            const int oi = p / 64, oj = p % 64;
            float m = -INFINITY;
#pragma unroll
            for (int di = 0; di < 2; di++)
#pragma unroll
                for (int dj = 0; dj < 2; dj++) {
                    const int idx = (2 * oi + di) * 128 + (2 * oj + dj);
                    float v = (ab[idx] - mean) * rstd * g1[idx] + be1[idx];
                    m = fmaxf(m, v);
                }
            s_pad[(oi + 2) * PW + (oj + 2)] = m;
        }
        __syncthreads();
    }

    float mean, rstd;

    // ---------------- L2: 64x64 k=5, no pool -------------------------------
    lc_sm<64, 5>(w2, b2, s_pad, s_act, mean, rstd, s_red);
    norm_store<64, false, 2, false>(s_act, g2, be2, mean, rstd, s_pad);

    // ---------------- L3: 64x64 k=5, pool -> 32x32 (OPAD=1 for k=3) --------
    lc_sm<64, 5>(w3, b3, s_pad, s_act, mean, rstd, s_red);
    norm_store<64, true, 1, false>(s_act, g3, be3, mean, rstd, s_pad);

    // ---------------- L4: 32x32 k=3, no pool -------------------------------
    lc_sm<32, 3>(w4, b4, s_pad, s_act, mean, rstd, s_red);
    norm_store<32, false, 1, false>(s_act, g4, be4, mean, rstd, s_pad);

    // ---------------- L5: 32x32 k=3, pool -> 16x16 -------------------------
    lc_sm<32, 3>(w5, b5, s_pad, s_act, mean, rstd, s_red);
    norm_store<32, true, 1, false>(s_act, g5, be5, mean, rstd, s_pad);

    // ---------------- L6: 16x16 k=3, no pool, FLAT output ------------------
    lc_sm<16, 3>(w6, b6, s_pad, s_act, mean, rstd, s_red);
    norm_store<16, false, 0, true>(s_act, g6, be6, mean, rstd, s_pad);
    // s_pad[0..255] now holds the flattened 256-d feature vector.

    // ---------------- FC 256->1024 + softmax -------------------------------
    {
        const int o = tid;                       // 1024 outputs, 1 per thread
        const float4* w4p = (const float4*)(fcw + (size_t)o * 256);
        const float4* x4  = (const float4*)s_pad;
        float acc = fcb[o];
#pragma unroll 8
        for (int k = 0; k < 64; k++) {
            float4 wv = w4p[k];
            float4 xv = x4[k];
            acc = fmaf(wv.x, xv.x, acc);
            acc = fmaf(wv.y, xv.y, acc);
            acc = fmaf(wv.z, xv.z, acc);
            acc = fmaf(wv.w, xv.w, acc);
        }
        const float M = block_max(acc, s_red);
        const float e = expf(acc - M);
        const float S = block_sum1(e, s_red);
        out[(size_t)b * 1024 + o] = e / S;
    }
}

// ===========================================================================
// Launch
// ===========================================================================
extern "C" void kernel_launch(void* const* d_in, const int* in_sizes, int n_in,
                              void* d_out, int out_size) {
    (void)in_sizes; (void)n_in; (void)out_size;

    const float* x   = (const float*)d_in[0];
    const float* w1  = (const float*)d_in[1];
    const float* b1  = (const float*)d_in[2];
    const float* g1  = (const float*)d_in[3];
    const float* be1 = (const float*)d_in[4];
    const float* w2  = (const float*)d_in[5];
    const float* b2  = (const float*)d_in[6];
    const float* g2  = (const float*)d_in[7];
    const float* be2 = (const float*)d_in[8];
    const float* w3  = (const float*)d_in[9];
    const float* b3  = (const float*)d_in[10];
    const float* g3  = (const float*)d_in[11];
    const float* be3 = (const float*)d_in[12];
    const float* w4  = (const float*)d_in[13];
    const float* b4  = (const float*)d_in[14];
    const float* g4  = (const float*)d_in[15];
    const float* be4 = (const float*)d_in[16];
    const float* w5  = (const float*)d_in[17];
    const float* b5  = (const float*)d_in[18];
    const float* g5  = (const float*)d_in[19];
    const float* be5 = (const float*)d_in[20];
    const float* w6  = (const float*)d_in[21];
    const float* b6  = (const float*)d_in[22];
    const float* g6  = (const float*)d_in[23];
    const float* be6 = (const float*)d_in[24];
    const float* fcw = (const float*)d_in[25];
    const float* fcb = (const float*)d_in[26];
    float* out = (float*)d_out;

    float* A;
    cudaGetSymbolAddress((void**)&A, g_bufA);

    // L1: 256 blocks x 512 threads, weights reused across 8 images
    lc1_kernel<4, 8><<<dim3(32, 8), 512>>>(x, w1, b1, A);

    // Everything else: one block per image
    fused_kernel<<<64, NTB>>>(A,
        g1, be1, w2, b2, g2, be2, w3, b3, g3, be3,
        w4, b4, g4, be4, w5, b5, g5, be5, w6, b6, g6, be6,
        fcw, fcb, out);
}

// round 5
// speedup vs baseline: 4.9596x; 1.6729x over previous
#include <cuda_runtime.h>
#include <cuda_bf16.h>
#include <math.h>

// ---------------------------------------------------------------------------
// Scratch (allocation-free device globals)
// ---------------------------------------------------------------------------
__device__ float  g_bufA[64 * 128 * 128];     // 4 MB   pre-norm L1 activations
__device__ float  g_wt1[16384 * 49];          // 3.2 MB w1 transposed  [k][pix]
__device__ float  g_wt2[4096 * 25];
__device__ float  g_wt3[4096 * 25];
__device__ float  g_wt4[1024 * 9];
__device__ float  g_wt5[1024 * 9];
__device__ float  g_wt6[256 * 9];
__device__ float4 g_fcwt[64 * 1024];          // 1 MB   fcw transposed [kk][o]

// ===========================================================================
// Tiled transpose of all LC weights: [N,K] -> [K,N], both sides coalesced.
// One block per 32-pixel tile. Grid = 512+128+128+32+32+8 = 840.
// ===========================================================================
__global__ __launch_bounds__(256) void transpose_lc(
    const float* __restrict__ w1, const float* __restrict__ w2,
    const float* __restrict__ w3, const float* __restrict__ w4,
    const float* __restrict__ w5, const float* __restrict__ w6,
    float* __restrict__ t1, float* __restrict__ t2, float* __restrict__ t3,
    float* __restrict__ t4, float* __restrict__ t5, float* __restrict__ t6) {
    __shared__ float s[32 * 49];
    int tile = blockIdx.x;
    const float* in; float* out; int N, K;
    if      (tile < 512) {             in = w1; out = t1; N = 16384; K = 49; }
    else if (tile < 640) { tile -= 512; in = w2; out = t2; N = 4096;  K = 25; }
    else if (tile < 768) { tile -= 640; in = w3; out = t3; N = 4096;  K = 25; }
    else if (tile < 800) { tile -= 768; in = w4; out = t4; N = 1024;  K = 9;  }
    else if (tile < 832) { tile -= 800; in = w5; out = t5; N = 1024;  K = 9;  }
    else                 { tile -= 832; in = w6; out = t6; N = 256;   K = 9;  }
    const int p0  = tile * 32;
    const int tot = 32 * K;
    const int tid = threadIdx.x;
    for (int idx = tid; idx < tot; idx += 256) s[idx] = in[(size_t)p0 * K + idx];
    __syncthreads();
    for (int idx = tid; idx < tot; idx += 256) {
        int k = idx >> 5, pl = idx & 31;
        out[(size_t)k * N + p0 + pl] = s[pl * K + k];
    }
}

// fcw [1024,256] viewed as float4 [1024,64] -> [64,1024].  32 blocks.
__global__ __launch_bounds__(256) void transpose_fc(const float4* __restrict__ in,
                                                    float4* __restrict__ out) {
    __shared__ float4 s[32 * 65];
    const int o0  = blockIdx.x * 32;
    const int tid = threadIdx.x;
    for (int idx = tid; idx < 32 * 64; idx += 256) {
        int ol = idx >> 6, kk = idx & 63;
        s[ol * 65 + kk] = in[(size_t)(o0 + ol) * 64 + kk];
    }
    __syncthreads();
    for (int idx = tid; idx < 32 * 64; idx += 256) {
        int kk = idx >> 5, ol = idx & 31;
        out[(size_t)kk * 1024 + o0 + ol] = s[ol * 65 + kk];
    }
}

// ===========================================================================
// Kernel A: L1 LC + ReLU (k-major weights, coalesced). Writes pre-norm acts.
// ===========================================================================
template <int RPB, int BCH>
__global__ __launch_bounds__(512) void lc1_kernel(const float* __restrict__ in,
                                                  const float* __restrict__ wt,
                                                  const float* __restrict__ bias,
                                                  float* __restrict__ act) {
    constexpr int H = 128, W = 128, K = 7, PAD = 3, KK = 49, N = H * W;
    constexpr int IW = W + 2 * PAD;
    constexpr int IR = RPB + 2 * PAD;
    constexpr int NT = RPB * W;

    __shared__ float sin[IR * IW];

    const int r0  = blockIdx.x * RPB;
    const int b0  = blockIdx.y * BCH;
    const int tid = threadIdx.x;
    const int li  = tid / W;
    const int lj  = tid % W;
    const int pix = (r0 + li) * W + lj;

    float wr[KK];
#pragma unroll
    for (int t = 0; t < KK; t++) wr[t] = wt[(size_t)t * N + pix];   // coalesced
    const float bb = bias[pix];

    for (int bi = 0; bi < BCH; bi++) {
        const int b = b0 + bi;
        const float* inb = in + (size_t)b * N;
        __syncthreads();
        for (int idx = tid; idx < IR * IW; idx += NT) {
            int r = idx / IW, c = idx % IW;
            int gi = r0 - PAD + r, gj = c - PAD;
            float v = 0.f;
            if (gi >= 0 && gi < H && gj >= 0 && gj < W) v = inb[gi * W + gj];
            sin[idx] = v;
        }
        __syncthreads();

        float sum = bb;
#pragma unroll
        for (int kh = 0; kh < K; kh++)
#pragma unroll
            for (int kw = 0; kw < K; kw++)
                sum = fmaf(wr[kh * K + kw], sin[(li + kh) * IW + (lj + kw)], sum);

        act[(size_t)b * N + pix] = fmaxf(sum, 0.f);
    }
}

// ===========================================================================
// Kernel B: fused L2..L6 + FC + softmax.  One block per image, 1024 threads.
// ===========================================================================
#define NTB 1024
#define PW  68

__device__ __forceinline__ void block_sum2(float& s, float& q, float* red) {
    __syncthreads();
#pragma unroll
    for (int o = 16; o > 0; o >>= 1) {
        s += __shfl_down_sync(0xffffffffu, s, o);
        q += __shfl_down_sync(0xffffffffu, q, o);
    }
    const int wid = threadIdx.x >> 5, lane = threadIdx.x & 31;
    if (lane == 0) { red[wid] = s; red[32 + wid] = q; }
    __syncthreads();
    if (wid == 0) {
        s = red[lane]; q = red[32 + lane];
#pragma unroll
        for (int o = 16; o > 0; o >>= 1) {
            s += __shfl_down_sync(0xffffffffu, s, o);
            q += __shfl_down_sync(0xffffffffu, q, o);
        }
        if (lane == 0) { red[0] = s; red[32] = q; }
    }
    __syncthreads();
    s = red[0]; q = red[32];
}

__device__ __forceinline__ float block_max(float v, float* red) {
    __syncthreads();
#pragma unroll
    for (int o = 16; o > 0; o >>= 1)
        v = fmaxf(v, __shfl_xor_sync(0xffffffffu, v, o));
    const int wid = threadIdx.x >> 5, lane = threadIdx.x & 31;
    if (lane == 0) red[wid] = v;
    __syncthreads();
    if (wid == 0) {
        v = red[lane];
#pragma unroll
        for (int o = 16; o > 0; o >>= 1)
            v = fmaxf(v, __shfl_xor_sync(0xffffffffu, v, o));
        if (lane == 0) red[0] = v;
    }
    __syncthreads();
    return red[0];
}

__device__ __forceinline__ float block_sum1(float v, float* red) {
    __syncthreads();
#pragma unroll
    for (int o = 16; o > 0; o >>= 1)
        v += __shfl_down_sync(0xffffffffu, v, o);
    const int wid = threadIdx.x >> 5, lane = threadIdx.x & 31;
    if (lane == 0) red[wid] = v;
    __syncthreads();
    if (wid == 0) {
        v = red[lane];
#pragma unroll
        for (int o = 16; o > 0; o >>= 1)
            v += __shfl_down_sync(0xffffffffu, v, o);
        if (lane == 0) red[0] = v;
    }
    __syncthreads();
    return red[0];
}

// LC from padded smem with k-major weights; relu; LN stats.
template <int H, int K>
__device__ __forceinline__ void lc_sm(const float* __restrict__ wt,
                                      const float* __restrict__ bias,
                                      const float* s_in, float* s_act,
                                      float& mean, float& rstd, float* red) {
    constexpr int N   = H * H;
    constexpr int PPT = (N + NTB - 1) / NTB;
    const int tid = threadIdx.x;

    float acc[PPT];
    int   base[PPT];
#pragma unroll
    for (int pp = 0; pp < PPT; pp++) {
        const int p = tid + pp * NTB;
        if (p < N) { acc[pp] = bias[p]; base[pp] = (p / H) * PW + (p % H); }
    }
#pragma unroll
    for (int kh = 0; kh < K; kh++)
#pragma unroll
        for (int kw = 0; kw < K; kw++) {
            const float* wk = wt + (size_t)(kh * K + kw) * N;
            const int off = kh * PW + kw;
#pragma unroll
            for (int pp = 0; pp < PPT; pp++) {
                const int p = tid + pp * NTB;
                if (p < N) acc[pp] = fmaf(wk[p], s_in[base[pp] + off], acc[pp]);
            }
        }

    float s = 0.f, q = 0.f;
#pragma unroll
    for (int pp = 0; pp < PPT; pp++) {
        const int p = tid + pp * NTB;
        if (p < N) {
            float v = fmaxf(acc[pp], 0.f);
            s_act[p] = v;
            s += v; q += v * v;
        }
    }
    block_sum2(s, q, red);
    const float m = s * (1.0f / N);
    mean = m;
    rstd = rsqrtf(q * (1.0f / N) - m * m + 1e-5f);
}

template <int H, bool POOL, int OPAD, bool FLAT>
__device__ __forceinline__ void norm_store(const float* s_act,
                                           const float* __restrict__ g,
                                           const float* __restrict__ be,
                                           float mean, float rstd, float* s_pad) {
    for (int p = threadIdx.x; p < PW * PW; p += NTB) s_pad[p] = 0.f;
    __syncthreads();
    if (!POOL) {
        for (int p = threadIdx.x; p < H * H; p += NTB) {
            const int i = p / H, j = p % H;
            float v = (s_act[p] - mean) * rstd * g[p] + be[p];
            if (FLAT) s_pad[p] = v;
            else      s_pad[(i + OPAD) * PW + (j + OPAD)] = v;
        }
    } else {
        constexpr int HO = H / 2;
        for (int p = threadIdx.x; p < HO * HO; p += NTB) {
            const int oi = p / HO, oj = p % HO;
            float m = -INFINITY;
#pragma unroll
            for (int di = 0; di < 2; di++)
#pragma unroll
                for (int dj = 0; dj < 2; dj++) {
                    const int idx = (2 * oi + di) * H + (2 * oj + dj);
                    float v = (s_act[idx] - mean) * rstd * g[idx] + be[idx];
                    m = fmaxf(m, v);
                }
            s_pad[(oi + OPAD) * PW + (oj + OPAD)] = m;
        }
    }
    __syncthreads();
}

__global__ __launch_bounds__(NTB) void fused_kernel(
    const float* __restrict__ bufA,
    const float* __restrict__ g1, const float* __restrict__ be1,
    const float* __restrict__ wt2, const float* __restrict__ b2,
    const float* __restrict__ g2, const float* __restrict__ be2,
    const float* __restrict__ wt3, const float* __restrict__ b3,
    const float* __restrict__ g3, const float* __restrict__ be3,
    const float* __restrict__ wt4, const float* __restrict__ b4,
    const float* __restrict__ g4, const float* __restrict__ be4,
    const float* __restrict__ wt5, const float* __restrict__ b5,
    const float* __restrict__ g5, const float* __restrict__ be5,
    const float* __restrict__ wt6, const float* __restrict__ b6,
    const float* __restrict__ g6, const float* __restrict__ be6,
    const float4* __restrict__ fcwt, const float* __restrict__ fcb,
    float* __restrict__ out) {

    __shared__ float s_pad[PW * PW];
    __shared__ float s_act[64 * 64];
    __shared__ float s_red[64];

    const int b   = blockIdx.x;
    const int tid = threadIdx.x;
    const float* ab = bufA + (size_t)b * 128 * 128;

    // ---------------- L1 stats + norm + pool -------------------------------
    {
        float s = 0.f, q = 0.f;
        const float4* a4 = (const float4*)ab;
        for (int p = tid; p < 128 * 128 / 4; p += NTB) {
            float4 v = a4[p];
            s += v.x + v.y + v.z + v.w;
            q += v.x * v.x + v.y * v.y + v.z * v.z + v.w * v.w;
        }
        block_sum2(s, q, s_red);
        const float mean = s * (1.0f / 16384.0f);
        const float rstd = rsqrtf(q * (1.0f / 16384.0f) - mean * mean + 1e-5f);

        for (int p = tid; p < PW * PW; p += NTB) s_pad[p] = 0.f;
        __syncthreads();
        for (int p = tid; p < 64 * 64; p += NTB) {
            const int oi = p / 64, oj = p % 64;
            float m = -INFINITY;
#pragma unroll
            for (int di = 0; di < 2; di++)
#pragma unroll
                for (int dj = 0; dj < 2; dj++) {
                    const int idx = (2 * oi + di) * 128 + (2 * oj + dj);
                    float v = (ab[idx] - mean) * rstd * g1[idx] + be1[idx];
                    m = fmaxf(m, v);
                }
            s_pad[(oi + 2) * PW + (oj + 2)] = m;
        }
        __syncthreads();
    }

    float mean, rstd;

    lc_sm<64, 5>(wt2, b2, s_pad, s_act, mean, rstd, s_red);
    norm_store<64, false, 2, false>(s_act, g2, be2, mean, rstd, s_pad);

    lc_sm<64, 5>(wt3, b3, s_pad, s_act, mean, rstd, s_red);
    norm_store<64, true, 1, false>(s_act, g3, be3, mean, rstd, s_pad);

    lc_sm<32, 3>(wt4, b4, s_pad, s_act, mean, rstd, s_red);
    norm_store<32, false, 1, false>(s_act, g4, be4, mean, rstd, s_pad);

    lc_sm<32, 3>(wt5, b5, s_pad, s_act, mean, rstd, s_red);
    norm_store<32, true, 1, false>(s_act, g5, be5, mean, rstd, s_pad);

    lc_sm<16, 3>(wt6, b6, s_pad, s_act, mean, rstd, s_red);
    norm_store<16, false, 0, true>(s_act, g6, be6, mean, rstd, s_pad);
    // s_pad[0..255] = flattened feature vector

    // ---------------- FC 256->1024 + softmax (k-major float4 weights) ------
    {
        const int o = tid;
        const float4* x4 = (const float4*)s_pad;
        float acc = fcb[o];
#pragma unroll 8
        for (int kk = 0; kk < 64; kk++) {
            float4 wv = fcwt[(size_t)kk * 1024 + o];   // 512B-contiguous per warp
            float4 xv = x4[kk];
            acc = fmaf(wv.x, xv.x, acc);
            acc = fmaf(wv.y, xv.y, acc);
            acc = fmaf(wv.z, xv.z, acc);
            acc = fmaf(wv.w, xv.w, acc);
        }
        const float M = block_max(acc, s_red);
        const float e = expf(acc - M);
        const float S = block_sum1(e, s_red);
        out[(size_t)b * 1024 + o] = e / S;
    }
}

// ===========================================================================
// Launch
// ===========================================================================
extern "C" void kernel_launch(void* const* d_in, const int* in_sizes, int n_in,
                              void* d_out, int out_size) {
    (void)in_sizes; (void)n_in; (void)out_size;

    const float* x   = (const float*)d_in[0];
    const float* w1  = (const float*)d_in[1];
    const float* b1  = (const float*)d_in[2];
    const float* g1  = (const float*)d_in[3];
    const float* be1 = (const float*)d_in[4];
    const float* w2  = (const float*)d_in[5];
    const float* b2  = (const float*)d_in[6];
    const float* g2  = (const float*)d_in[7];
    const float* be2 = (const float*)d_in[8];
    const float* w3  = (const float*)d_in[9];
    const float* b3  = (const float*)d_in[10];
    const float* g3  = (const float*)d_in[11];
    const float* be3 = (const float*)d_in[12];
    const float* w4  = (const float*)d_in[13];
    const float* b4  = (const float*)d_in[14];
    const float* g4  = (const float*)d_in[15];
    const float* be4 = (const float*)d_in[16];
    const float* w5  = (const float*)d_in[17];
    const float* b5  = (const float*)d_in[18];
    const float* g5  = (const float*)d_in[19];
    const float* be5 = (const float*)d_in[20];
    const float* w6  = (const float*)d_in[21];
    const float* b6  = (const float*)d_in[22];
    const float* g6  = (const float*)d_in[23];
    const float* be6 = (const float*)d_in[24];
    const float* fcw = (const float*)d_in[25];
    const float* fcb = (const float*)d_in[26];
    float* out = (float*)d_out;

    float *A, *t1, *t2, *t3, *t4, *t5, *t6;
    float4* fct;
    cudaGetSymbolAddress((void**)&A,   g_bufA);
    cudaGetSymbolAddress((void**)&t1,  g_wt1);
    cudaGetSymbolAddress((void**)&t2,  g_wt2);
    cudaGetSymbolAddress((void**)&t3,  g_wt3);
    cudaGetSymbolAddress((void**)&t4,  g_wt4);
    cudaGetSymbolAddress((void**)&t5,  g_wt5);
    cudaGetSymbolAddress((void**)&t6,  g_wt6);
    cudaGetSymbolAddress((void**)&fct, g_fcwt);

    transpose_lc<<<840, 256>>>(w1, w2, w3, w4, w5, w6, t1, t2, t3, t4, t5, t6);
    transpose_fc<<<32, 256>>>((const float4*)fcw, fct);

    lc1_kernel<4, 8><<<dim3(32, 8), 512>>>(x, t1, b1, A);

    fused_kernel<<<64, NTB>>>(A,
        g1, be1, t2, b2, g2, be2, t3, b3, g3, be3,
        t4, b4, g4, be4, t5, b5, g5, be5, t6, b6, g6, be6,
        fct, fcb, out);
}